// round 2
// baseline (speedup 1.0000x reference)
#include <cuda_runtime.h>
#include <math.h>
#include <stdint.h>

#define Bsz  16
#define Ntok 2048
#define Cdim 768
#define BN   (Bsz*Ntok)

// ---------------- scratch (static device globals; no allocation) ------------
__device__ float g_y [(size_t)BN*Cdim];          // conv+residual output (x1)
__device__ float g_x2[(size_t)BN*Cdim];          // layernormed x
__device__ float g_wp[3*Cdim*Cdim];              // packed conv weights [k][co][ci]
__device__ float g_dist[(size_t)Bsz*Ntok*Ntok];  // 268 MB distance matrix
__device__ float g_tw [BN];                      // token weight exp(score)
__device__ float g_sq [BN];                      // sum x2^2 per token
__device__ float g_den[BN];                      // density
__device__ float g_sc [BN];                      // dist_min * density
__device__ float g_dmax[Bsz];
__device__ int   g_idn[Bsz*2];
__device__ float g_aw [Bsz*2];
__device__ int   g_cl [BN];
__device__ float g_nw [BN];

// ---------------- small helpers ---------------------------------------------
__device__ __forceinline__ void ins3(float v, float& c0, float& c1, float& c2) {
    if (v < c2) {
        if (v < c1) {
            c2 = c1;
            if (v < c0) { c1 = c0; c0 = v; } else c1 = v;
        } else c2 = v;
    }
}

__global__ void k_init() {
    int t = threadIdx.x;
    if (t < Bsz) g_dmax[t] = 0.0f;
}

__global__ void k_pack(const float* __restrict__ w) {
    int i = blockIdx.x * 256 + threadIdx.x;
    if (i >= 3 * Cdim * Cdim) return;
    int ci = i % Cdim;
    int co = (i / Cdim) % Cdim;
    int k  = i / (Cdim * Cdim);
    g_wp[i] = w[((size_t)co * Cdim + ci) * 3 + k];
}

// ---------------- GEMM: conv taps (C = Cin + A_shift * Wk^T) ---------------
// 128x128x8 tile, 8x8 per thread, 256 threads.
__global__ void __launch_bounds__(256) k_conv(const float* __restrict__ x, int k) {
    __shared__ float As[8][128];
    __shared__ float Bs[8][128];
    const int K = Cdim;
    const int shift = k - 1;
    const float* __restrict__ Bw  = g_wp + (size_t)k * Cdim * Cdim;
    const float* __restrict__ Cin = (k == 0) ? x : g_y;
    float* __restrict__ Cout = g_y;

    int m0 = blockIdx.y * 128, n0 = blockIdx.x * 128;
    int t = threadIdx.x;
    int lr = t >> 1, lseg = (t & 1) * 4;
    int tx = t & 15, ty = t >> 4;

    float acc[8][8];
    #pragma unroll
    for (int i = 0; i < 8; i++)
        #pragma unroll
        for (int j = 0; j < 8; j++) acc[i][j] = 0.f;

    for (int k0 = 0; k0 < K; k0 += 8) {
        int m  = m0 + lr;
        int ns = (m & (Ntok - 1)) + shift;
        float4 av = make_float4(0.f, 0.f, 0.f, 0.f);
        if (ns >= 0 && ns < Ntok)
            av = *(const float4*)(x + (size_t)(m + shift) * K + k0 + lseg);
        As[lseg + 0][lr] = av.x; As[lseg + 1][lr] = av.y;
        As[lseg + 2][lr] = av.z; As[lseg + 3][lr] = av.w;
        float4 bv = *(const float4*)(Bw + (size_t)(n0 + lr) * K + k0 + lseg);
        Bs[lseg + 0][lr] = bv.x; Bs[lseg + 1][lr] = bv.y;
        Bs[lseg + 2][lr] = bv.z; Bs[lseg + 3][lr] = bv.w;
        __syncthreads();
        #pragma unroll
        for (int kk = 0; kk < 8; kk++) {
            float4 a0 = *(const float4*)&As[kk][ty * 8];
            float4 a1 = *(const float4*)&As[kk][ty * 8 + 4];
            float4 b0 = *(const float4*)&Bs[kk][tx * 8];
            float4 b1 = *(const float4*)&Bs[kk][tx * 8 + 4];
            float a[8] = {a0.x, a0.y, a0.z, a0.w, a1.x, a1.y, a1.z, a1.w};
            float b[8] = {b0.x, b0.y, b0.z, b0.w, b1.x, b1.y, b1.z, b1.w};
            #pragma unroll
            for (int i = 0; i < 8; i++)
                #pragma unroll
                for (int j = 0; j < 8; j++)
                    acc[i][j] = fmaf(a[i], b[j], acc[i][j]);
        }
        __syncthreads();
    }
    #pragma unroll
    for (int i = 0; i < 8; i++) {
        size_t off = (size_t)(m0 + ty * 8 + i) * Cdim + n0 + tx * 8;
        float4 c0 = *(const float4*)(Cin + off);
        float4 c1 = *(const float4*)(Cin + off + 4);
        c0.x += acc[i][0]; c0.y += acc[i][1]; c0.z += acc[i][2]; c0.w += acc[i][3];
        c1.x += acc[i][4]; c1.y += acc[i][5]; c1.z += acc[i][6]; c1.w += acc[i][7];
        *(float4*)(Cout + off)     = c0;
        *(float4*)(Cout + off + 4) = c1;
    }
}

// ---------------- LayerNorm + score + sumsq ---------------------------------
__global__ void __launch_bounds__(256) k_ln(const float* __restrict__ gma,
                                            const float* __restrict__ bta,
                                            const float* __restrict__ sw,
                                            const float* __restrict__ sb) {
    __shared__ float r1[256], r2[256];
    int row = blockIdx.x;
    const float* x = g_y + (size_t)row * Cdim;
    int t = threadIdx.x;
    float v0 = x[t], v1 = x[t + 256], v2 = x[t + 512];
    r1[t] = v0 + v1 + v2;
    r2[t] = v0 * v0 + v1 * v1 + v2 * v2;
    __syncthreads();
    for (int h = 128; h; h >>= 1) {
        if (t < h) { r1[t] += r1[t + h]; r2[t] += r2[t + h]; }
        __syncthreads();
    }
    float mu  = r1[0] * (1.f / Cdim);
    float var = r2[0] * (1.f / Cdim) - mu * mu;
    float rstd = rsqrtf(var + 1e-5f);
    __syncthreads();
    float y0 = (v0 - mu) * rstd * gma[t]       + bta[t];
    float y1 = (v1 - mu) * rstd * gma[t + 256] + bta[t + 256];
    float y2 = (v2 - mu) * rstd * gma[t + 512] + bta[t + 512];
    float* o = g_x2 + (size_t)row * Cdim;
    o[t] = y0; o[t + 256] = y1; o[t + 512] = y2;
    r1[t] = y0 * sw[t] + y1 * sw[t + 256] + y2 * sw[t + 512];
    r2[t] = y0 * y0 + y1 * y1 + y2 * y2;
    __syncthreads();
    for (int h = 128; h; h >>= 1) {
        if (t < h) { r1[t] += r1[t + h]; r2[t] += r2[t + h]; }
        __syncthreads();
    }
    if (t == 0) {
        g_tw[row] = expf(r1[0] + sb[0]);
        g_sq[row] = r2[0];
    }
}

// ---------------- GEMM: per-batch gram -> distance matrix -------------------
__global__ void __launch_bounds__(256) k_gram() {
    __shared__ float As[8][128];
    __shared__ float Bs[8][128];
    const int K = Cdim;
    int bz = blockIdx.z;
    const float* __restrict__ X = g_x2 + (size_t)bz * Ntok * Cdim;
    float* __restrict__ D = g_dist + (size_t)bz * Ntok * Ntok;
    const float* __restrict__ sqb = g_sq + bz * Ntok;

    int m0 = blockIdx.y * 128, n0 = blockIdx.x * 128;
    int t = threadIdx.x;
    int lr = t >> 1, lseg = (t & 1) * 4;
    int tx = t & 15, ty = t >> 4;

    float acc[8][8];
    #pragma unroll
    for (int i = 0; i < 8; i++)
        #pragma unroll
        for (int j = 0; j < 8; j++) acc[i][j] = 0.f;

    for (int k0 = 0; k0 < K; k0 += 8) {
        float4 av = *(const float4*)(X + (size_t)(m0 + lr) * K + k0 + lseg);
        As[lseg + 0][lr] = av.x; As[lseg + 1][lr] = av.y;
        As[lseg + 2][lr] = av.z; As[lseg + 3][lr] = av.w;
        float4 bv = *(const float4*)(X + (size_t)(n0 + lr) * K + k0 + lseg);
        Bs[lseg + 0][lr] = bv.x; Bs[lseg + 1][lr] = bv.y;
        Bs[lseg + 2][lr] = bv.z; Bs[lseg + 3][lr] = bv.w;
        __syncthreads();
        #pragma unroll
        for (int kk = 0; kk < 8; kk++) {
            float4 a0 = *(const float4*)&As[kk][ty * 8];
            float4 a1 = *(const float4*)&As[kk][ty * 8 + 4];
            float4 b0 = *(const float4*)&Bs[kk][tx * 8];
            float4 b1 = *(const float4*)&Bs[kk][tx * 8 + 4];
            float a[8] = {a0.x, a0.y, a0.z, a0.w, a1.x, a1.y, a1.z, a1.w};
            float b[8] = {b0.x, b0.y, b0.z, b0.w, b1.x, b1.y, b1.z, b1.w};
            #pragma unroll
            for (int i = 0; i < 8; i++)
                #pragma unroll
                for (int j = 0; j < 8; j++)
                    acc[i][j] = fmaf(a[i], b[j], acc[i][j]);
        }
        __syncthreads();
    }
    const float rs = rsqrtf((float)Cdim);
    float sm[8];
    #pragma unroll
    for (int j = 0; j < 8; j++) sm[j] = sqb[n0 + tx * 8 + j];
    #pragma unroll
    for (int i = 0; i < 8; i++) {
        float sn = sqb[m0 + ty * 8 + i];
        float r[8];
        #pragma unroll
        for (int j = 0; j < 8; j++) {
            float d2 = sn + sm[j] - 2.f * acc[i][j];
            r[j] = sqrtf(fmaxf(d2, 0.f)) * rs;
        }
        size_t off = (size_t)(m0 + ty * 8 + i) * Ntok + n0 + tx * 8;
        *(float4*)(D + off)     = make_float4(r[0], r[1], r[2], r[3]);
        *(float4*)(D + off + 4) = make_float4(r[4], r[5], r[6], r[7]);
    }
}

// ---------------- per-row: top-3 smallest + row max -> density --------------
__global__ void __launch_bounds__(256) k_top3(const float* __restrict__ noise) {
    int n = blockIdx.x, b = blockIdx.y;
    const float* row = g_dist + ((size_t)b * Ntok + n) * Ntok;
    int t = threadIdx.x;
    float c0 = 3e38f, c1 = 3e38f, c2 = 3e38f, mx = 0.f;
    for (int m = t; m < Ntok; m += 256) {
        float v = row[m];
        mx = fmaxf(mx, v);
        ins3(v, c0, c1, c2);
    }
    __shared__ float s0[256], s1[256], s2[256], sm[256];
    s0[t] = c0; s1[t] = c1; s2[t] = c2; sm[t] = mx;
    __syncthreads();
    for (int h = 128; h; h >>= 1) {
        if (t < h) {
            float b0 = s0[t + h], b1 = s1[t + h], b2 = s2[t + h];
            c0 = s0[t]; c1 = s1[t]; c2 = s2[t];
            ins3(b0, c0, c1, c2); ins3(b1, c0, c1, c2); ins3(b2, c0, c1, c2);
            s0[t] = c0; s1[t] = c1; s2[t] = c2;
            sm[t] = fmaxf(sm[t], sm[t + h]);
        }
        __syncthreads();
    }
    if (t == 0) {
        float m3 = (s0[0] * s0[0] + s1[0] * s1[0] + s2[0] * s2[0]) * (1.f / 3.f);
        g_den[b * Ntok + n] = expf(-m3) + noise[b * Ntok + n] * 1e-6f;
        atomicMax((int*)&g_dmax[b], __float_as_int(sm[0]));
    }
}

// ---------------- per-row: dist to nearest higher-density -> score ----------
__global__ void __launch_bounds__(256) k_dmin() {
    int n = blockIdx.x, b = blockIdx.y;
    const float* row = g_dist + ((size_t)b * Ntok + n) * Ntok;
    const float* den = g_den + b * Ntok;
    float dn = den[n];
    float dmax = g_dmax[b];
    int t = threadIdx.x;
    float mn = 3e38f;
    for (int m = t; m < Ntok; m += 256) {
        float v = (den[m] > dn) ? row[m] : dmax;
        mn = fminf(mn, v);
    }
    __shared__ float s[256];
    s[t] = mn; __syncthreads();
    for (int h = 128; h; h >>= 1) {
        if (t < h) s[t] = fminf(s[t], s[t + h]);
        __syncthreads();
    }
    if (t == 0) g_sc[b * Ntok + n] = s[0] * dn;
}

// ---------------- per-batch: top-2 score indices ----------------------------
__global__ void __launch_bounds__(256) k_top2() {
    int b = blockIdx.x, t = threadIdx.x;
    const float* sc = g_sc + b * Ntok;
    __shared__ float bv[256];
    __shared__ int   bi[256];
    float v = -3e38f; int ii = 0x7fffffff;
    for (int m = t; m < Ntok; m += 256) {
        float x = sc[m];
        if (x > v) { v = x; ii = m; }
    }
    bv[t] = v; bi[t] = ii; __syncthreads();
    for (int h = 128; h; h >>= 1) {
        if (t < h) {
            if (bv[t + h] > bv[t] || (bv[t + h] == bv[t] && bi[t + h] < bi[t])) {
                bv[t] = bv[t + h]; bi[t] = bi[t + h];
            }
        }
        __syncthreads();
    }
    int i0 = bi[0];
    __syncthreads();
    v = -3e38f; ii = 0x7fffffff;
    for (int m = t; m < Ntok; m += 256) {
        if (m == i0) continue;
        float x = sc[m];
        if (x > v) { v = x; ii = m; }
    }
    bv[t] = v; bi[t] = ii; __syncthreads();
    for (int h = 128; h; h >>= 1) {
        if (t < h) {
            if (bv[t + h] > bv[t] || (bv[t + h] == bv[t] && bi[t + h] < bi[t])) {
                bv[t] = bv[t + h]; bi[t] = bi[t + h];
            }
        }
        __syncthreads();
    }
    if (t == 0) {
        g_idn[2 * b]     = i0;
        g_idn[2 * b + 1] = bi[0];
        g_aw[2 * b]      = 1e-6f;
        g_aw[2 * b + 1]  = 1e-6f;
    }
}

// ---------------- assign clusters + accumulate cluster weights --------------
__global__ void __launch_bounds__(256) k_assign() {
    int tk = blockIdx.x * 256 + threadIdx.x;
    int b = tk >> 11, n = tk & (Ntok - 1);
    int i0 = g_idn[2 * b], i1 = g_idn[2 * b + 1];
    float d0 = g_dist[((size_t)b * Ntok + i0) * Ntok + n];
    float d1 = g_dist[((size_t)b * Ntok + i1) * Ntok + n];
    int cl = (d1 < d0) ? 1 : 0;
    if (n == i0) cl = 0;
    if (n == i1) cl = 1;
    g_cl[tk] = cl;
    float w = g_tw[tk];
    float w0 = cl ? 0.f : w;
    float w1 = cl ? w : 0.f;
    #pragma unroll
    for (int o = 16; o; o >>= 1) {
        w0 += __shfl_down_sync(0xffffffffu, w0, o);
        w1 += __shfl_down_sync(0xffffffffu, w1, o);
    }
    if ((threadIdx.x & 31) == 0) {
        atomicAdd(&g_aw[2 * b],     w0);
        atomicAdd(&g_aw[2 * b + 1], w1);
    }
}

// ---------------- normalized weights + aux outputs --------------------------
__global__ void __launch_bounds__(256) k_norm(float* __restrict__ out, int out_size) {
    int tk = blockIdx.x * 256 + threadIdx.x;
    int b = tk >> 11;
    int cl = g_cl[tk];
    float nw = g_tw[tk] / g_aw[2 * b + cl];
    g_nw[tk] = nw;
    const int XM = Bsz * 2 * Cdim;       // 24576
    if (out_size >= XM + BN)       out[XM + tk]      = nw;
    if (out_size >= XM + 2 * BN)   out[XM + BN + tk] = (float)cl;
}

// ---------------- weighted merge into 2 clusters per batch ------------------
__global__ void __launch_bounds__(128) k_merge(float* __restrict__ out) {
    int b = blockIdx.y;
    int c = blockIdx.x * 128 + threadIdx.x;
    const float* X  = g_x2 + (size_t)b * Ntok * Cdim + c;
    const float* nw = g_nw + b * Ntok;
    const int*   cl = g_cl + b * Ntok;
    float a0 = 0.f, a1 = 0.f;
    for (int n = 0; n < Ntok; n++) {
        float w  = nw[n];
        float xv = X[(size_t)n * Cdim];
        if (cl[n] == 0) a0 = fmaf(xv, w, a0);
        else            a1 = fmaf(xv, w, a1);
    }
    out[((size_t)b * 2 + 0) * Cdim + c] = a0;
    out[((size_t)b * 2 + 1) * Cdim + c] = a1;
}

// ---------------- launch ----------------------------------------------------
extern "C" void kernel_launch(void* const* d_in, const int* in_sizes, int n_in,
                              void* d_out, int out_size) {
    const float* x     = (const float*)d_in[0];
    const float* cw    = (const float*)d_in[1];
    const float* gma   = (const float*)d_in[2];
    const float* bta   = (const float*)d_in[3];
    const float* sw    = (const float*)d_in[4];
    const float* sb    = (const float*)d_in[5];
    const float* noise = (const float*)d_in[6];
    float* out = (float*)d_out;

    k_init<<<1, 32>>>();
    k_pack<<<(3 * Cdim * Cdim + 255) / 256, 256>>>(cw);

    dim3 gc(Cdim / 128, BN / 128);      // (6, 256)
    for (int k = 0; k < 3; k++)
        k_conv<<<gc, 256>>>(x, k);

    k_ln<<<BN, 256>>>(gma, bta, sw, sb);

    dim3 gg(Ntok / 128, Ntok / 128, Bsz);  // (16, 16, 16)
    k_gram<<<gg, 256>>>();

    dim3 gr(Ntok, Bsz);
    k_top3<<<gr, 256>>>(noise);
    k_dmin<<<gr, 256>>>();
    k_top2<<<Bsz, 256>>>();
    k_assign<<<BN / 256, 256>>>();
    k_norm<<<BN / 256, 256>>>(out, out_size);
    dim3 gm(Cdim / 128, Bsz);
    k_merge<<<gm, 128>>>(out);
}

// round 4
// speedup vs baseline: 1.0178x; 1.0178x over previous
#include <cuda_runtime.h>
#include <math.h>
#include <stdint.h>

#define Bsz  16
#define Ntok 2048
#define Cdim 768
#define BN   (Bsz*Ntok)

typedef unsigned long long ull;

// ---------------- scratch (static device globals; no allocation) ------------
__device__ float g_y [(size_t)BN*Cdim];          // conv+residual output
__device__ float g_x2[(size_t)BN*Cdim];          // layernormed x
__device__ float g_wp[3*Cdim*Cdim];              // packed conv weights [k][co][ci]
__device__ float g_dist[(size_t)Bsz*Ntok*Ntok];  // 268 MB distance matrix
__device__ float g_tw [BN];                      // token weight exp(score)
__device__ float g_sq [BN];                      // sum x2^2 per token
__device__ float g_den[BN];                      // density
__device__ float g_sc [BN];                      // dist_min * density
__device__ float g_dmax[Bsz];
__device__ int   g_idn[Bsz*2];
__device__ float g_aw [Bsz*2];
__device__ int   g_cl [BN];
__device__ float g_nw [BN];

// ---------------- helpers ----------------------------------------------------
#define FMA2(c, a, b) asm("fma.rn.f32x2 %0, %1, %2, %0;" : "+l"(c) : "l"(a), "l"(b))

__device__ __forceinline__ void ins3(float v, float& c0, float& c1, float& c2) {
    if (v < c2) {
        if (v < c1) {
            c2 = c1;
            if (v < c0) { c1 = c0; c0 = v; } else c1 = v;
        } else c2 = v;
    }
}

__global__ void k_init() {
    int t = threadIdx.x;
    if (t < Bsz) g_dmax[t] = 0.0f;
}

__global__ void k_pack(const float* __restrict__ w) {
    int i = blockIdx.x * 256 + threadIdx.x;
    if (i >= 3 * Cdim * Cdim) return;
    int ci = i % Cdim;
    int co = (i / Cdim) % Cdim;
    int k  = i / (Cdim * Cdim);
    g_wp[i] = w[((size_t)co * Cdim + ci) * 3 + k];
}

// ---------------- fused conv GEMM: y = x + sum_k shift(x,k-1) * Wk^T --------
// 128x128 tile, 8x8/thread via f32x2, double-buffered smem, 3 taps fused.
__global__ void __launch_bounds__(256, 2) k_conv(const float* __restrict__ x) {
    __shared__ float As[2][8][256];   // A values duplicated (a,a) pairs
    __shared__ float Bs[2][8][128];

    const int m0 = blockIdx.y * 128, n0 = blockIdx.x * 128;
    const int t = threadIdx.x;
    const int lr = t >> 1, lseg = (t & 1) * 4;
    const int tx = t & 15, ty = t >> 4;

    ull acc[8][4];
    #pragma unroll
    for (int i = 0; i < 8; i++)
        #pragma unroll
        for (int j = 0; j < 4; j++) acc[i][j] = 0ull;

    const int NSTEP = 3 * (Cdim / 8);   // 288

    // fetch step s into registers
    float4 av, bv;
    {
        const int s = 0;
        int tap = s / (Cdim / 8), k0 = (s % (Cdim / 8)) * 8;
        int m = m0 + lr;
        int ns = (m & (Ntok - 1)) + tap - 1;
        av = make_float4(0.f, 0.f, 0.f, 0.f);
        if (ns >= 0 && ns < Ntok)
            av = *(const float4*)(x + (size_t)(m + tap - 1) * Cdim + k0 + lseg);
        bv = *(const float4*)(g_wp + (size_t)tap * Cdim * Cdim + (size_t)(n0 + lr) * Cdim + k0 + lseg);
    }
    // store stage 0
    As[0][lseg + 0][2 * lr] = av.x; As[0][lseg + 0][2 * lr + 1] = av.x;
    As[0][lseg + 1][2 * lr] = av.y; As[0][lseg + 1][2 * lr + 1] = av.y;
    As[0][lseg + 2][2 * lr] = av.z; As[0][lseg + 2][2 * lr + 1] = av.z;
    As[0][lseg + 3][2 * lr] = av.w; As[0][lseg + 3][2 * lr + 1] = av.w;
    Bs[0][lseg + 0][lr] = bv.x; Bs[0][lseg + 1][lr] = bv.y;
    Bs[0][lseg + 2][lr] = bv.z; Bs[0][lseg + 3][lr] = bv.w;
    __syncthreads();

    int st = 0;
    for (int s = 0; s < NSTEP; s++) {
        bool has = (s + 1) < NSTEP;
        if (has) {
            const int sn = s + 1;
            int tap = sn / (Cdim / 8), k0 = (sn % (Cdim / 8)) * 8;
            int m = m0 + lr;
            int ns = (m & (Ntok - 1)) + tap - 1;
            av = make_float4(0.f, 0.f, 0.f, 0.f);
            if (ns >= 0 && ns < Ntok)
                av = *(const float4*)(x + (size_t)(m + tap - 1) * Cdim + k0 + lseg);
            bv = *(const float4*)(g_wp + (size_t)tap * Cdim * Cdim + (size_t)(n0 + lr) * Cdim + k0 + lseg);
        }
        #pragma unroll
        for (int kk = 0; kk < 8; kk++) {
            ulonglong2 A0 = *(const ulonglong2*)&As[st][kk][ty * 16];
            ulonglong2 A1 = *(const ulonglong2*)&As[st][kk][ty * 16 + 4];
            ulonglong2 A2 = *(const ulonglong2*)&As[st][kk][ty * 16 + 8];
            ulonglong2 A3 = *(const ulonglong2*)&As[st][kk][ty * 16 + 12];
            ulonglong2 B0 = *(const ulonglong2*)&Bs[st][kk][tx * 8];
            ulonglong2 B1 = *(const ulonglong2*)&Bs[st][kk][tx * 8 + 4];
            ull ap[8] = {A0.x, A0.y, A1.x, A1.y, A2.x, A2.y, A3.x, A3.y};
            ull bp[4] = {B0.x, B0.y, B1.x, B1.y};
            #pragma unroll
            for (int i = 0; i < 8; i++) {
                FMA2(acc[i][0], ap[i], bp[0]);
                FMA2(acc[i][1], ap[i], bp[1]);
                FMA2(acc[i][2], ap[i], bp[2]);
                FMA2(acc[i][3], ap[i], bp[3]);
            }
        }
        if (has) {
            int so = st ^ 1;
            As[so][lseg + 0][2 * lr] = av.x; As[so][lseg + 0][2 * lr + 1] = av.x;
            As[so][lseg + 1][2 * lr] = av.y; As[so][lseg + 1][2 * lr + 1] = av.y;
            As[so][lseg + 2][2 * lr] = av.z; As[so][lseg + 2][2 * lr + 1] = av.z;
            As[so][lseg + 3][2 * lr] = av.w; As[so][lseg + 3][2 * lr + 1] = av.w;
            Bs[so][lseg + 0][lr] = bv.x; Bs[so][lseg + 1][lr] = bv.y;
            Bs[so][lseg + 2][lr] = bv.z; Bs[so][lseg + 3][lr] = bv.w;
            __syncthreads();
            st = so;
        }
    }

    #pragma unroll
    for (int i = 0; i < 8; i++) {
        size_t off = (size_t)(m0 + ty * 8 + i) * Cdim + n0 + tx * 8;
        float4 c0 = *(const float4*)(x + off);
        float4 c1 = *(const float4*)(x + off + 4);
        float2 p0 = *(float2*)&acc[i][0];
        float2 p1 = *(float2*)&acc[i][1];
        float2 p2 = *(float2*)&acc[i][2];
        float2 p3 = *(float2*)&acc[i][3];
        c0.x += p0.x; c0.y += p0.y; c0.z += p1.x; c0.w += p1.y;
        c1.x += p2.x; c1.y += p2.y; c1.z += p3.x; c1.w += p3.y;
        *(float4*)(g_y + off)     = c0;
        *(float4*)(g_y + off + 4) = c1;
    }
}

// ---------------- LayerNorm + score + sumsq ---------------------------------
__global__ void __launch_bounds__(256) k_ln(const float* __restrict__ gma,
                                            const float* __restrict__ bta,
                                            const float* __restrict__ sw,
                                            const float* __restrict__ sb) {
    __shared__ float r1[256], r2[256];
    int row = blockIdx.x;
    const float* x = g_y + (size_t)row * Cdim;
    int t = threadIdx.x;
    float v0 = x[t], v1 = x[t + 256], v2 = x[t + 512];
    r1[t] = v0 + v1 + v2;
    r2[t] = v0 * v0 + v1 * v1 + v2 * v2;
    __syncthreads();
    for (int h = 128; h; h >>= 1) {
        if (t < h) { r1[t] += r1[t + h]; r2[t] += r2[t + h]; }
        __syncthreads();
    }
    float mu  = r1[0] * (1.f / Cdim);
    float var = r2[0] * (1.f / Cdim) - mu * mu;
    float rstd = rsqrtf(var + 1e-5f);
    __syncthreads();
    float y0 = (v0 - mu) * rstd * gma[t]       + bta[t];
    float y1 = (v1 - mu) * rstd * gma[t + 256] + bta[t + 256];
    float y2 = (v2 - mu) * rstd * gma[t + 512] + bta[t + 512];
    float* o = g_x2 + (size_t)row * Cdim;
    o[t] = y0; o[t + 256] = y1; o[t + 512] = y2;
    r1[t] = y0 * sw[t] + y1 * sw[t + 256] + y2 * sw[t + 512];
    r2[t] = y0 * y0 + y1 * y1 + y2 * y2;
    __syncthreads();
    for (int h = 128; h; h >>= 1) {
        if (t < h) { r1[t] += r1[t + h]; r2[t] += r2[t + h]; }
        __syncthreads();
    }
    if (t == 0) {
        g_tw[row] = expf(r1[0] + sb[0]);
        g_sq[row] = r2[0];
    }
}

// ---------------- gram -> dist, upper-triangle tiles only + mirror ----------
__global__ void __launch_bounds__(256, 2) k_gram() {
    __shared__ float As[2][8][256];   // duplicated pairs
    __shared__ float Bs[2][8][128];
    __shared__ float Tr[32][132];     // transpose staging (padded, 16B-aligned rows)

    // decode upper-triangle tile (mi, ni), ni >= mi
    int rem = blockIdx.x, mi = 0;
    #pragma unroll 1
    while (rem >= 16 - mi) { rem -= 16 - mi; mi++; }
    int ni = mi + rem;

    const int bz = blockIdx.z;
    const float* __restrict__ X = g_x2 + (size_t)bz * Ntok * Cdim;
    float* __restrict__ D = g_dist + (size_t)bz * Ntok * Ntok;
    const float* __restrict__ sqb = g_sq + bz * Ntok;

    const int m0 = mi * 128, n0 = ni * 128;
    const int t = threadIdx.x;
    const int lr = t >> 1, lseg = (t & 1) * 4;
    const int tx = t & 15, ty = t >> 4;

    ull acc[8][4];
    #pragma unroll
    for (int i = 0; i < 8; i++)
        #pragma unroll
        for (int j = 0; j < 4; j++) acc[i][j] = 0ull;

    float4 av = *(const float4*)(X + (size_t)(m0 + lr) * Cdim + lseg);
    float4 bv = *(const float4*)(X + (size_t)(n0 + lr) * Cdim + lseg);
    As[0][lseg + 0][2 * lr] = av.x; As[0][lseg + 0][2 * lr + 1] = av.x;
    As[0][lseg + 1][2 * lr] = av.y; As[0][lseg + 1][2 * lr + 1] = av.y;
    As[0][lseg + 2][2 * lr] = av.z; As[0][lseg + 2][2 * lr + 1] = av.z;
    As[0][lseg + 3][2 * lr] = av.w; As[0][lseg + 3][2 * lr + 1] = av.w;
    Bs[0][lseg + 0][lr] = bv.x; Bs[0][lseg + 1][lr] = bv.y;
    Bs[0][lseg + 2][lr] = bv.z; Bs[0][lseg + 3][lr] = bv.w;
    __syncthreads();

    int st = 0;
    for (int k0 = 0; k0 < Cdim; k0 += 8) {
        bool has = (k0 + 8) < Cdim;
        if (has) {
            av = *(const float4*)(X + (size_t)(m0 + lr) * Cdim + k0 + 8 + lseg);
            bv = *(const float4*)(X + (size_t)(n0 + lr) * Cdim + k0 + 8 + lseg);
        }
        #pragma unroll
        for (int kk = 0; kk < 8; kk++) {
            ulonglong2 A0 = *(const ulonglong2*)&As[st][kk][ty * 16];
            ulonglong2 A1 = *(const ulonglong2*)&As[st][kk][ty * 16 + 4];
            ulonglong2 A2 = *(const ulonglong2*)&As[st][kk][ty * 16 + 8];
            ulonglong2 A3 = *(const ulonglong2*)&As[st][kk][ty * 16 + 12];
            ulonglong2 B0 = *(const ulonglong2*)&Bs[st][kk][tx * 8];
            ulonglong2 B1 = *(const ulonglong2*)&Bs[st][kk][tx * 8 + 4];
            ull ap[8] = {A0.x, A0.y, A1.x, A1.y, A2.x, A2.y, A3.x, A3.y};
            ull bp[4] = {B0.x, B0.y, B1.x, B1.y};
            #pragma unroll
            for (int i = 0; i < 8; i++) {
                FMA2(acc[i][0], ap[i], bp[0]);
                FMA2(acc[i][1], ap[i], bp[1]);
                FMA2(acc[i][2], ap[i], bp[2]);
                FMA2(acc[i][3], ap[i], bp[3]);
            }
        }
        if (has) {
            int so = st ^ 1;
            As[so][lseg + 0][2 * lr] = av.x; As[so][lseg + 0][2 * lr + 1] = av.x;
            As[so][lseg + 1][2 * lr] = av.y; As[so][lseg + 1][2 * lr + 1] = av.y;
            As[so][lseg + 2][2 * lr] = av.z; As[so][lseg + 2][2 * lr + 1] = av.z;
            As[so][lseg + 3][2 * lr] = av.w; As[so][lseg + 3][2 * lr + 1] = av.w;
            Bs[so][lseg + 0][lr] = bv.x; Bs[so][lseg + 1][lr] = bv.y;
            Bs[so][lseg + 2][lr] = bv.z; Bs[so][lseg + 3][lr] = bv.w;
            __syncthreads();
            st = so;
        }
    }

    const float rs = rsqrtf((float)Cdim);
    float sn8[8], sm8[8];
    #pragma unroll
    for (int j = 0; j < 8; j++) sm8[j] = sqb[n0 + tx * 8 + j];
    #pragma unroll
    for (int i = 0; i < 8; i++) sn8[i] = sqb[m0 + ty * 8 + i];

    // direct write: rows m0.., cols n0..
    #pragma unroll
    for (int i = 0; i < 8; i++) {
        float r[8];
        #pragma unroll
        for (int j = 0; j < 4; j++) {
            float2 p = *(float2*)&acc[i][j];
            float d2a = sn8[i] + sm8[2 * j]     - 2.f * p.x;
            float d2b = sn8[i] + sm8[2 * j + 1] - 2.f * p.y;
            r[2 * j]     = sqrtf(fmaxf(d2a, 0.f)) * rs;
            r[2 * j + 1] = sqrtf(fmaxf(d2b, 0.f)) * rs;
        }
        size_t off = (size_t)(m0 + ty * 8 + i) * Ntok + n0 + tx * 8;
        *(float4*)(D + off)     = make_float4(r[0], r[1], r[2], r[3]);
        *(float4*)(D + off + 4) = make_float4(r[4], r[5], r[6], r[7]);
    }

    // mirror write for off-diagonal tiles via smem transpose
    if (ni > mi) {
        const int cc0 = tx >> 2;              // this thread's 32-col chunk
        for (int cc = 0; cc < 4; cc++) {
            __syncthreads();
            if (cc == cc0) {
                #pragma unroll
                for (int i = 0; i < 8; i++) {
                    #pragma unroll
                    for (int j = 0; j < 4; j++) {
                        float2 p = *(float2*)&acc[i][j];
                        float d2a = sn8[i] + sm8[2 * j]     - 2.f * p.x;
                        float d2b = sn8[i] + sm8[2 * j + 1] - 2.f * p.y;
                        Tr[(tx & 3) * 8 + 2 * j][ty * 8 + i]     = sqrtf(fmaxf(d2a, 0.f)) * rs;
                        Tr[(tx & 3) * 8 + 2 * j + 1][ty * 8 + i] = sqrtf(fmaxf(d2b, 0.f)) * rs;
                    }
                }
            }
            __syncthreads();
            #pragma unroll
            for (int it = 0; it < 2; it++) {
                int r = (t >> 4) + it * 16;
                int c = (t & 15) * 8;
                float4 v0 = *(const float4*)&Tr[r][c];
                float4 v1 = *(const float4*)&Tr[r][c + 4];
                size_t off = (size_t)(n0 + cc * 32 + r) * Ntok + m0 + c;
                *(float4*)(D + off)     = v0;
                *(float4*)(D + off + 4) = v1;
            }
        }
    }
}

// ---------------- per-row: top-3 smallest + row max -> density --------------
__global__ void __launch_bounds__(256) k_top3(const float* __restrict__ noise) {
    int n = blockIdx.x, b = blockIdx.y;
    const float* row = g_dist + ((size_t)b * Ntok + n) * Ntok;
    int t = threadIdx.x;
    float c0 = 3e38f, c1 = 3e38f, c2 = 3e38f, mx = 0.f;
    for (int m = t; m < Ntok; m += 256) {
        float v = row[m];
        mx = fmaxf(mx, v);
        ins3(v, c0, c1, c2);
    }
    __shared__ float s0[256], s1[256], s2[256], sm[256];
    s0[t] = c0; s1[t] = c1; s2[t] = c2; sm[t] = mx;
    __syncthreads();
    for (int h = 128; h; h >>= 1) {
        if (t < h) {
            float b0 = s0[t + h], b1 = s1[t + h], b2 = s2[t + h];
            c0 = s0[t]; c1 = s1[t]; c2 = s2[t];
            ins3(b0, c0, c1, c2); ins3(b1, c0, c1, c2); ins3(b2, c0, c1, c2);
            s0[t] = c0; s1[t] = c1; s2[t] = c2;
            sm[t] = fmaxf(sm[t], sm[t + h]);
        }
        __syncthreads();
    }
    if (t == 0) {
        float m3 = (s0[0] * s0[0] + s1[0] * s1[0] + s2[0] * s2[0]) * (1.f / 3.f);
        g_den[b * Ntok + n] = expf(-m3) + noise[b * Ntok + n] * 1e-6f;
        atomicMax((int*)&g_dmax[b], __float_as_int(sm[0]));
    }
}

// ---------------- per-row: dist to nearest higher-density -> score ----------
__global__ void __launch_bounds__(256) k_dmin() {
    int n = blockIdx.x, b = blockIdx.y;
    const float* row = g_dist + ((size_t)b * Ntok + n) * Ntok;
    const float* den = g_den + b * Ntok;
    float dn = den[n];
    float dmax = g_dmax[b];
    int t = threadIdx.x;
    float mn = 3e38f;
    for (int m = t; m < Ntok; m += 256) {
        float v = (den[m] > dn) ? row[m] : dmax;
        mn = fminf(mn, v);
    }
    __shared__ float s[256];
    s[t] = mn; __syncthreads();
    for (int h = 128; h; h >>= 1) {
        if (t < h) s[t] = fminf(s[t], s[t + h]);
        __syncthreads();
    }
    if (t == 0) g_sc[b * Ntok + n] = s[0] * dn;
}

// ---------------- per-batch: top-2 score indices ----------------------------
__global__ void __launch_bounds__(256) k_top2() {
    int b = blockIdx.x, t = threadIdx.x;
    const float* sc = g_sc + b * Ntok;
    __shared__ float bv[256];
    __shared__ int   bi[256];
    float v = -3e38f; int ii = 0x7fffffff;
    for (int m = t; m < Ntok; m += 256) {
        float x = sc[m];
        if (x > v) { v = x; ii = m; }
    }
    bv[t] = v; bi[t] = ii; __syncthreads();
    for (int h = 128; h; h >>= 1) {
        if (t < h) {
            if (bv[t + h] > bv[t] || (bv[t + h] == bv[t] && bi[t + h] < bi[t])) {
                bv[t] = bv[t + h]; bi[t] = bi[t + h];
            }
        }
        __syncthreads();
    }
    int i0 = bi[0];
    __syncthreads();
    v = -3e38f; ii = 0x7fffffff;
    for (int m = t; m < Ntok; m += 256) {
        if (m == i0) continue;
        float x = sc[m];
        if (x > v) { v = x; ii = m; }
    }
    bv[t] = v; bi[t] = ii; __syncthreads();
    for (int h = 128; h; h >>= 1) {
        if (t < h) {
            if (bv[t + h] > bv[t] || (bv[t + h] == bv[t] && bi[t + h] < bi[t])) {
                bv[t] = bv[t + h]; bi[t] = bi[t + h];
            }
        }
        __syncthreads();
    }
    if (t == 0) {
        g_idn[2 * b]     = i0;
        g_idn[2 * b + 1] = bi[0];
        g_aw[2 * b]      = 1e-6f;
        g_aw[2 * b + 1]  = 1e-6f;
    }
}

// ---------------- assign clusters + accumulate cluster weights --------------
__global__ void __launch_bounds__(256) k_assign() {
    int tk = blockIdx.x * 256 + threadIdx.x;
    int b = tk >> 11, n = tk & (Ntok - 1);
    int i0 = g_idn[2 * b], i1 = g_idn[2 * b + 1];
    float d0 = g_dist[((size_t)b * Ntok + i0) * Ntok + n];
    float d1 = g_dist[((size_t)b * Ntok + i1) * Ntok + n];
    int cl = (d1 < d0) ? 1 : 0;
    if (n == i0) cl = 0;
    if (n == i1) cl = 1;
    g_cl[tk] = cl;
    float w = g_tw[tk];
    float w0 = cl ? 0.f : w;
    float w1 = cl ? w : 0.f;
    #pragma unroll
    for (int o = 16; o; o >>= 1) {
        w0 += __shfl_down_sync(0xffffffffu, w0, o);
        w1 += __shfl_down_sync(0xffffffffu, w1, o);
    }
    if ((threadIdx.x & 31) == 0) {
        atomicAdd(&g_aw[2 * b],     w0);
        atomicAdd(&g_aw[2 * b + 1], w1);
    }
}

// ---------------- normalized weights + aux outputs --------------------------
__global__ void __launch_bounds__(256) k_norm(float* __restrict__ out, int out_size) {
    int tk = blockIdx.x * 256 + threadIdx.x;
    int b = tk >> 11;
    int cl = g_cl[tk];
    float nw = g_tw[tk] / g_aw[2 * b + cl];
    g_nw[tk] = nw;
    const int XM = Bsz * 2 * Cdim;       // 24576
    if (out_size >= XM + BN)       out[XM + tk]      = nw;
    if (out_size >= XM + 2 * BN)   out[XM + BN + tk] = (float)cl;
}

// ---------------- weighted merge into 2 clusters per batch ------------------
__global__ void __launch_bounds__(128) k_merge(float* __restrict__ out) {
    int b = blockIdx.y;
    int c = blockIdx.x * 128 + threadIdx.x;
    const float* X  = g_x2 + (size_t)b * Ntok * Cdim + c;
    const float* nw = g_nw + b * Ntok;
    const int*   cl = g_cl + b * Ntok;
    float a0 = 0.f, a1 = 0.f;
    for (int n = 0; n < Ntok; n++) {
        float w  = nw[n];
        float xv = X[(size_t)n * Cdim];
        if (cl[n] == 0) a0 = fmaf(xv, w, a0);
        else            a1 = fmaf(xv, w, a1);
    }
    out[((size_t)b * 2 + 0) * Cdim + c] = a0;
    out[((size_t)b * 2 + 1) * Cdim + c] = a1;
}

// ---------------- launch ----------------------------------------------------
extern "C" void kernel_launch(void* const* d_in, const int* in_sizes, int n_in,
                              void* d_out, int out_size) {
    const float* x     = (const float*)d_in[0];
    const float* cw    = (const float*)d_in[1];
    const float* gma   = (const float*)d_in[2];
    const float* bta   = (const float*)d_in[3];
    const float* sw    = (const float*)d_in[4];
    const float* sb    = (const float*)d_in[5];
    const float* noise = (const float*)d_in[6];
    float* out = (float*)d_out;

    k_init<<<1, 32>>>();
    k_pack<<<(3 * Cdim * Cdim + 255) / 256, 256>>>(cw);

    dim3 gc(Cdim / 128, BN / 128);      // (6, 256)
    k_conv<<<gc, 256>>>(x);

    k_ln<<<BN, 256>>>(gma, bta, sw, sb);

    dim3 gg(136, 1, Bsz);               // upper-triangle tiles per batch
    k_gram<<<gg, 256>>>();

    dim3 gr(Ntok, Bsz);
    k_top3<<<gr, 256>>>(noise);
    k_dmin<<<gr, 256>>>();
    k_top2<<<Bsz, 256>>>();
    k_assign<<<BN / 256, 256>>>();
    k_norm<<<BN / 256, 256>>>(out, out_size);
    dim3 gm(Cdim / 128, Bsz);
    k_merge<<<gm, 128>>>(out);
}

// round 9
// speedup vs baseline: 2.5291x; 2.4848x over previous
#include <cuda_runtime.h>
#include <cuda_bf16.h>
#include <math.h>
#include <stdint.h>

#define Bsz  16
#define Ntok 2048
#define Cdim 768
#define BN   (Bsz*Ntok)

// ---------------- scratch (static device globals; no allocation) ------------
__device__ float g_y [(size_t)BN*Cdim];                 // conv+residual output
__device__ float g_x2[(size_t)BN*Cdim];                 // layernormed x
__device__ __align__(16) __nv_bfloat16 g_xh[(size_t)BN*Cdim];   // hi split
__device__ __align__(16) __nv_bfloat16 g_xl[(size_t)BN*Cdim];   // lo split
__device__ __align__(16) __nv_bfloat16 g_wh[3*Cdim*Cdim];       // W hi [tap][co][ci]
__device__ __align__(16) __nv_bfloat16 g_wl[3*Cdim*Cdim];       // W lo
__device__ float g_dist[(size_t)Bsz*Ntok*Ntok];         // 268 MB distance matrix
__device__ float g_tw [BN];
__device__ float g_sq [BN];
__device__ float g_den[BN];
__device__ float g_sc [BN];
__device__ float g_dmax[Bsz];
__device__ int   g_idn[Bsz*2];
__device__ float g_aw [Bsz*2];
__device__ int   g_cl [BN];
__device__ float g_nw [BN];

// ---------------- mma/ldmatrix/cp.async helpers ------------------------------
__device__ __forceinline__ uint32_t smem_u32(const void* p) {
    uint32_t a;
    asm("{ .reg .u64 t; cvta.to.shared.u64 t, %1; cvt.u32.u64 %0, t; }"
        : "=r"(a) : "l"(p));
    return a;
}

__device__ __forceinline__ void cpa16(uint32_t d, const void* s, int sz) {
    asm volatile("cp.async.cg.shared.global [%0], [%1], 16, %2;"
                 :: "r"(d), "l"(s), "r"(sz));
}

__device__ __forceinline__ void ldm4(uint32_t* r, uint32_t a) {
    asm volatile("ldmatrix.sync.aligned.m8n8.x4.shared.b16 {%0,%1,%2,%3}, [%4];"
                 : "=r"(r[0]), "=r"(r[1]), "=r"(r[2]), "=r"(r[3]) : "r"(a));
}

__device__ __forceinline__ void mma16816(float* c, const uint32_t* a, const uint32_t* b) {
    asm volatile(
        "mma.sync.aligned.m16n8k16.row.col.f32.bf16.bf16.f32 "
        "{%0,%1,%2,%3}, {%4,%5,%6,%7}, {%8,%9}, {%0,%1,%2,%3};"
        : "+f"(c[0]), "+f"(c[1]), "+f"(c[2]), "+f"(c[3])
        : "r"(a[0]), "r"(a[1]), "r"(a[2]), "r"(a[3]), "r"(b[0]), "r"(b[1]));
}

// smem geometry: 4 matrices of 128 rows x 32 bf16, row pitch 80B, 2 stages
#define PITCH 80
#define MATB  (128*PITCH)     // 10240
#define A_HI  0
#define A_LO  (1*MATB)
#define B_HI  (2*MATB)
#define B_LO  (3*MATB)
#define STG   (4*MATB)        // 40960
#define SMEM_DYN (2*STG)      // 81920

// ---------------- misc small kernels ----------------------------------------
__global__ void k_init() {
    int t = threadIdx.x;
    if (t < Bsz) g_dmax[t] = 0.0f;
}

__global__ void k_splitw(const float* __restrict__ w) {
    int i = blockIdx.x * 256 + threadIdx.x;
    if (i >= 3 * Cdim * Cdim) return;
    int ci = i % Cdim;
    int co = (i / Cdim) % Cdim;
    int k  = i / (Cdim * Cdim);
    float v = w[((size_t)co * Cdim + ci) * 3 + k];
    __nv_bfloat16 h = __float2bfloat16(v);
    g_wh[i] = h;
    g_wl[i] = __float2bfloat16(v - __bfloat162float(h));
}

__device__ __forceinline__ void split4(const float* src, size_t i) {
    float4 v = *(const float4*)(src + i);
    __nv_bfloat16 h0 = __float2bfloat16(v.x), h1 = __float2bfloat16(v.y);
    __nv_bfloat16 h2 = __float2bfloat16(v.z), h3 = __float2bfloat16(v.w);
    __nv_bfloat162* ph = (__nv_bfloat162*)(g_xh + i);
    __nv_bfloat162* pl = (__nv_bfloat162*)(g_xl + i);
    ph[0] = __nv_bfloat162(h0, h1);
    ph[1] = __nv_bfloat162(h2, h3);
    pl[0] = __nv_bfloat162(__float2bfloat16(v.x - __bfloat162float(h0)),
                           __float2bfloat16(v.y - __bfloat162float(h1)));
    pl[1] = __nv_bfloat162(__float2bfloat16(v.z - __bfloat162float(h2)),
                           __float2bfloat16(v.w - __bfloat162float(h3)));
}

__global__ void __launch_bounds__(256) k_split_in(const float* __restrict__ src) {
    split4(src, ((size_t)blockIdx.x * 256 + threadIdx.x) * 4);
}
__global__ void __launch_bounds__(256) k_split_x2() {
    split4(g_x2, ((size_t)blockIdx.x * 256 + threadIdx.x) * 4);
}

// ---------------- shared GEMM core (per k-chunk compute) ---------------------
__device__ __forceinline__ void gemm_chunk(uint32_t st, int wm, int wn, int l,
                                           float acc[4][4][4]) {
    #pragma unroll
    for (int kh = 0; kh < 2; kh++) {
        uint32_t ah[4][4], al[4][4], bh[4][2], bl[4][2];
        uint32_t aoff = ((l >> 4) * 8 + kh * 16) * 2;
        int arow = wm * 64 + (l & 15);
        #pragma unroll
        for (int mt = 0; mt < 4; mt++) {
            ldm4(ah[mt], st + A_HI + (uint32_t)(arow + mt * 16) * PITCH + aoff);
            ldm4(al[mt], st + A_LO + (uint32_t)(arow + mt * 16) * PITCH + aoff);
        }
        int brow = wn * 32 + (l & 7) + ((l >> 4) & 1) * 8;
        uint32_t boff = (((l >> 3) & 1) * 8 + kh * 16) * 2;
        #pragma unroll
        for (int p = 0; p < 2; p++) {
            uint32_t tmp[4];
            ldm4(tmp, st + B_HI + (uint32_t)(brow + p * 16) * PITCH + boff);
            bh[2 * p][0] = tmp[0]; bh[2 * p][1] = tmp[1];
            bh[2 * p + 1][0] = tmp[2]; bh[2 * p + 1][1] = tmp[3];
            ldm4(tmp, st + B_LO + (uint32_t)(brow + p * 16) * PITCH + boff);
            bl[2 * p][0] = tmp[0]; bl[2 * p][1] = tmp[1];
            bl[2 * p + 1][0] = tmp[2]; bl[2 * p + 1][1] = tmp[3];
        }
        #pragma unroll
        for (int mt = 0; mt < 4; mt++)
            #pragma unroll
            for (int nt = 0; nt < 4; nt++) {
                mma16816(acc[mt][nt], ah[mt], bh[nt]);
                mma16816(acc[mt][nt], ah[mt], bl[nt]);
                mma16816(acc[mt][nt], al[mt], bh[nt]);
            }
    }
}

// ---------------- conv via HMMA: y = x + sum_taps shift(x)*Wk^T --------------
__device__ __forceinline__ void conv_load(uint32_t st, int r, int sg,
                                          int m0, int n0, int c) {
    int tap = c / 24, kc = (c % 24) * 32;
    int m = m0 + r;
    int loc = (m & (Ntok - 1)) + tap - 1;
    bool v = (loc >= 0 && loc < Ntok);
    long long ao = (long long)(m + tap - 1) * Cdim + kc;
    size_t wo = ((size_t)tap * Cdim + n0 + r) * Cdim + kc;
    uint32_t ro = (uint32_t)r * PITCH;
    #pragma unroll
    for (int i = 0; i < 2; i++) {
        int seg = sg + i;
        uint32_t so = ro + seg * 16;
        cpa16(st + A_HI + so, v ? (const void*)(g_xh + ao + seg * 8) : (const void*)g_xh, v ? 16 : 0);
        cpa16(st + A_LO + so, v ? (const void*)(g_xl + ao + seg * 8) : (const void*)g_xl, v ? 16 : 0);
        cpa16(st + B_HI + so, g_wh + wo + seg * 8, 16);
        cpa16(st + B_LO + so, g_wl + wo + seg * 8, 16);
    }
    asm volatile("cp.async.commit_group;");
}

__global__ void __launch_bounds__(256) k_conv_mma(const float* __restrict__ x) {
    extern __shared__ char sm[];
    uint32_t sb = smem_u32(sm);
    int t = threadIdx.x, l = t & 31, w = t >> 5;
    int wm = w & 1, wn = w >> 1;
    int m0 = blockIdx.y * 128, n0 = blockIdx.x * 128;
    int r = t >> 1, sg = (t & 1) * 2;

    float acc[4][4][4];
    #pragma unroll
    for (int i = 0; i < 4; i++)
        #pragma unroll
        for (int j = 0; j < 4; j++)
            #pragma unroll
            for (int q = 0; q < 4; q++) acc[i][j][q] = 0.f;

    const int C = 72;
    conv_load(sb, r, sg, m0, n0, 0);
    for (int c = 0; c < C; c++) {
        if (c + 1 < C) {
            conv_load(sb + ((c + 1) & 1) * STG, r, sg, m0, n0, c + 1);
            asm volatile("cp.async.wait_group 1;");
        } else {
            asm volatile("cp.async.wait_group 0;");
        }
        __syncthreads();
        gemm_chunk(sb + (c & 1) * STG, wm, wn, l, acc);
        __syncthreads();
    }

    #pragma unroll
    for (int mt = 0; mt < 4; mt++)
        #pragma unroll
        for (int nt = 0; nt < 4; nt++) {
            int mm = m0 + wm * 64 + mt * 16 + (l >> 2);
            int nn = n0 + wn * 32 + nt * 8 + (l & 3) * 2;
            size_t o0 = (size_t)mm * Cdim + nn;
            float2 xv = *(const float2*)(x + o0);
            float2 r0 = make_float2(xv.x + acc[mt][nt][0], xv.y + acc[mt][nt][1]);
            *(float2*)(g_y + o0) = r0;
            size_t o1 = o0 + (size_t)8 * Cdim;
            xv = *(const float2*)(x + o1);
            float2 r1 = make_float2(xv.x + acc[mt][nt][2], xv.y + acc[mt][nt][3]);
            *(float2*)(g_y + o1) = r1;
        }
}

// ---------------- LayerNorm + score + sumsq ---------------------------------
__global__ void __launch_bounds__(256) k_ln(const float* __restrict__ gma,
                                            const float* __restrict__ bta,
                                            const float* __restrict__ sw,
                                            const float* __restrict__ sb) {
    __shared__ float r1[256], r2[256];
    int row = blockIdx.x;
    const float* x = g_y + (size_t)row * Cdim;
    int t = threadIdx.x;
    float v0 = x[t], v1 = x[t + 256], v2 = x[t + 512];
    r1[t] = v0 + v1 + v2;
    r2[t] = v0 * v0 + v1 * v1 + v2 * v2;
    __syncthreads();
    for (int h = 128; h; h >>= 1) {
        if (t < h) { r1[t] += r1[t + h]; r2[t] += r2[t + h]; }
        __syncthreads();
    }
    float mu  = r1[0] * (1.f / Cdim);
    float var = r2[0] * (1.f / Cdim) - mu * mu;
    float rstd = rsqrtf(var + 1e-5f);
    __syncthreads();
    float y0 = (v0 - mu) * rstd * gma[t]       + bta[t];
    float y1 = (v1 - mu) * rstd * gma[t + 256] + bta[t + 256];
    float y2 = (v2 - mu) * rstd * gma[t + 512] + bta[t + 512];
    float* o = g_x2 + (size_t)row * Cdim;
    o[t] = y0; o[t + 256] = y1; o[t + 512] = y2;
    r1[t] = y0 * sw[t] + y1 * sw[t + 256] + y2 * sw[t + 512];
    r2[t] = y0 * y0 + y1 * y1 + y2 * y2;
    __syncthreads();
    for (int h = 128; h; h >>= 1) {
        if (t < h) { r1[t] += r1[t + h]; r2[t] += r2[t + h]; }
        __syncthreads();
    }
    if (t == 0) {
        g_tw[row] = expf(r1[0] + sb[0]);
        g_sq[row] = r2[0];
    }
}

// ---------------- gram via HMMA -> distance matrix (triangle+mirror) --------
__device__ __forceinline__ void gram_load(uint32_t st, int r, int sg,
                                          int bz, int m0, int n0, int c) {
    int kc = c * 32;
    size_t ao = ((size_t)(bz * Ntok + m0 + r)) * Cdim + kc;
    size_t bo = ((size_t)(bz * Ntok + n0 + r)) * Cdim + kc;
    uint32_t ro = (uint32_t)r * PITCH;
    #pragma unroll
    for (int i = 0; i < 2; i++) {
        int seg = sg + i;
        uint32_t so = ro + seg * 16;
        cpa16(st + A_HI + so, g_xh + ao + seg * 8, 16);
        cpa16(st + A_LO + so, g_xl + ao + seg * 8, 16);
        cpa16(st + B_HI + so, g_xh + bo + seg * 8, 16);
        cpa16(st + B_LO + so, g_xl + bo + seg * 8, 16);
    }
    asm volatile("cp.async.commit_group;");
}

__global__ void __launch_bounds__(256) k_gram_mma() {
    extern __shared__ char sm[];
    uint32_t sb = smem_u32(sm);
    int t = threadIdx.x, l = t & 31, w = t >> 5;
    int wm = w & 1, wn = w >> 1;

    int rem = blockIdx.x, mi = 0;
    #pragma unroll 1
    while (rem >= 16 - mi) { rem -= 16 - mi; mi++; }
    int ni = mi + rem;
    const int bz = blockIdx.z;
    const int m0 = mi * 128, n0 = ni * 128;
    float* __restrict__ D = g_dist + (size_t)bz * Ntok * Ntok;
    const float* __restrict__ sqb = g_sq + bz * Ntok;
    int r = t >> 1, sg = (t & 1) * 2;

    float acc[4][4][4];
    #pragma unroll
    for (int i = 0; i < 4; i++)
        #pragma unroll
        for (int j = 0; j < 4; j++)
            #pragma unroll
            for (int q = 0; q < 4; q++) acc[i][j][q] = 0.f;

    const int C = 24;
    gram_load(sb, r, sg, bz, m0, n0, 0);
    for (int c = 0; c < C; c++) {
        if (c + 1 < C) {
            gram_load(sb + ((c + 1) & 1) * STG, r, sg, bz, m0, n0, c + 1);
            asm volatile("cp.async.wait_group 1;");
        } else {
            asm volatile("cp.async.wait_group 0;");
        }
        __syncthreads();
        gemm_chunk(sb + (c & 1) * STG, wm, wn, l, acc);
        __syncthreads();
    }

    const float rs = rsqrtf((float)Cdim);
    #pragma unroll
    for (int mt = 0; mt < 4; mt++)
        #pragma unroll
        for (int nt = 0; nt < 4; nt++) {
            int mmb = m0 + wm * 64 + mt * 16 + (l >> 2);
            int nn = n0 + wn * 32 + nt * 8 + (l & 3) * 2;
            float s0 = sqb[nn], s1 = sqb[nn + 1];
            #pragma unroll
            for (int h = 0; h < 2; h++) {
                int M = mmb + h * 8;
                float sn = sqb[M];
                float d0 = sqrtf(fmaxf(sn + s0 - 2.f * acc[mt][nt][2 * h], 0.f)) * rs;
                float d1 = sqrtf(fmaxf(sn + s1 - 2.f * acc[mt][nt][2 * h + 1], 0.f)) * rs;
                *(float2*)(D + (size_t)M * Ntok + nn) = make_float2(d0, d1);
                if (ni > mi) {
                    D[(size_t)nn * Ntok + M]       = d0;
                    D[(size_t)(nn + 1) * Ntok + M] = d1;
                }
            }
        }
}

// ---------------- small helpers for scans -----------------------------------
__device__ __forceinline__ void ins3(float v, float& c0, float& c1, float& c2) {
    if (v < c2) {
        if (v < c1) {
            c2 = c1;
            if (v < c0) { c1 = c0; c0 = v; } else c1 = v;
        } else c2 = v;
    }
}

// ---------------- per-row: top-3 smallest + row max -> density --------------
__global__ void __launch_bounds__(256) k_top3(const float* __restrict__ noise) {
    int n = blockIdx.x, b = blockIdx.y;
    const float* row = g_dist + ((size_t)b * Ntok + n) * Ntok;
    int t = threadIdx.x;
    float c0 = 3e38f, c1 = 3e38f, c2 = 3e38f, mx = 0.f;
    for (int m = t; m < Ntok; m += 256) {
        float v = row[m];
        mx = fmaxf(mx, v);
        ins3(v, c0, c1, c2);
    }
    __shared__ float s0[256], s1[256], s2[256], smx[256];
    s0[t] = c0; s1[t] = c1; s2[t] = c2; smx[t] = mx;
    __syncthreads();
    for (int h = 128; h; h >>= 1) {
        if (t < h) {
            float b0 = s0[t + h], b1 = s1[t + h], b2 = s2[t + h];
            c0 = s0[t]; c1 = s1[t]; c2 = s2[t];
            ins3(b0, c0, c1, c2); ins3(b1, c0, c1, c2); ins3(b2, c0, c1, c2);
            s0[t] = c0; s1[t] = c1; s2[t] = c2;
            smx[t] = fmaxf(smx[t], smx[t + h]);
        }
        __syncthreads();
    }
    if (t == 0) {
        float m3 = (s0[0] * s0[0] + s1[0] * s1[0] + s2[0] * s2[0]) * (1.f / 3.f);
        g_den[b * Ntok + n] = expf(-m3) + noise[b * Ntok + n] * 1e-6f;
        atomicMax((int*)&g_dmax[b], __float_as_int(smx[0]));
    }
}

// ---------------- per-row: dist to nearest higher-density -> score ----------
__global__ void __launch_bounds__(256) k_dmin() {
    int n = blockIdx.x, b = blockIdx.y;
    const float* row = g_dist + ((size_t)b * Ntok + n) * Ntok;
    const float* den = g_den + b * Ntok;
    float dn = den[n];
    float dmax = g_dmax[b];
    int t = threadIdx.x;
    float mn = 3e38f;
    for (int m = t; m < Ntok; m += 256) {
        float v = (den[m] > dn) ? row[m] : dmax;
        mn = fminf(mn, v);
    }
    __shared__ float s[256];
    s[t] = mn; __syncthreads();
    for (int h = 128; h; h >>= 1) {
        if (t < h) s[t] = fminf(s[t], s[t + h]);
        __syncthreads();
    }
    if (t == 0) g_sc[b * Ntok + n] = s[0] * dn;
}

// ---------------- per-batch: top-2 score indices ----------------------------
__global__ void __launch_bounds__(256) k_top2() {
    int b = blockIdx.x, t = threadIdx.x;
    const float* sc = g_sc + b * Ntok;
    __shared__ float bv[256];
    __shared__ int   bi[256];
    float v = -3e38f; int ii = 0x7fffffff;
    for (int m = t; m < Ntok; m += 256) {
        float x = sc[m];
        if (x > v) { v = x; ii = m; }
    }
    bv[t] = v; bi[t] = ii; __syncthreads();
    for (int h = 128; h; h >>= 1) {
        if (t < h) {
            if (bv[t + h] > bv[t] || (bv[t + h] == bv[t] && bi[t + h] < bi[t])) {
                bv[t] = bv[t + h]; bi[t] = bi[t + h];
            }
        }
        __syncthreads();
    }
    int i0 = bi[0];
    __syncthreads();
    v = -3e38f; ii = 0x7fffffff;
    for (int m = t; m < Ntok; m += 256) {
        if (m == i0) continue;
        float x = sc[m];
        if (x > v) { v = x; ii = m; }
    }
    bv[t] = v; bi[t] = ii; __syncthreads();
    for (int h = 128; h; h >>= 1) {
        if (t < h) {
            if (bv[t + h] > bv[t] || (bv[t + h] == bv[t] && bi[t + h] < bi[t])) {
                bv[t] = bv[t + h]; bi[t] = bi[t + h];
            }
        }
        __syncthreads();
    }
    if (t == 0) {
        g_idn[2 * b]     = i0;
        g_idn[2 * b + 1] = bi[0];
        g_aw[2 * b]      = 1e-6f;
        g_aw[2 * b + 1]  = 1e-6f;
    }
}

// ---------------- assign clusters + accumulate cluster weights --------------
__global__ void __launch_bounds__(256) k_assign() {
    int tk = blockIdx.x * 256 + threadIdx.x;
    int b = tk >> 11, n = tk & (Ntok - 1);
    int i0 = g_idn[2 * b], i1 = g_idn[2 * b + 1];
    float d0 = g_dist[((size_t)b * Ntok + i0) * Ntok + n];
    float d1 = g_dist[((size_t)b * Ntok + i1) * Ntok + n];
    int cl = (d1 < d0) ? 1 : 0;
    if (n == i0) cl = 0;
    if (n == i1) cl = 1;
    g_cl[tk] = cl;
    float w = g_tw[tk];
    float w0 = cl ? 0.f : w;
    float w1 = cl ? w : 0.f;
    #pragma unroll
    for (int o = 16; o; o >>= 1) {
        w0 += __shfl_down_sync(0xffffffffu, w0, o);
        w1 += __shfl_down_sync(0xffffffffu, w1, o);
    }
    if ((threadIdx.x & 31) == 0) {
        atomicAdd(&g_aw[2 * b],     w0);
        atomicAdd(&g_aw[2 * b + 1], w1);
    }
}

// ---------------- normalized weights + aux outputs --------------------------
__global__ void __launch_bounds__(256) k_norm(float* __restrict__ out, int out_size) {
    int tk = blockIdx.x * 256 + threadIdx.x;
    int b = tk >> 11;
    int cl = g_cl[tk];
    float nw = g_tw[tk] / g_aw[2 * b + cl];
    g_nw[tk] = nw;
    const int XM = Bsz * 2 * Cdim;       // 24576
    if (out_size >= XM + BN)       out[XM + tk]      = nw;
    if (out_size >= XM + 2 * BN)   out[XM + BN + tk] = (float)cl;
}

// ---------------- weighted merge into 2 clusters per batch ------------------
__global__ void __launch_bounds__(128) k_merge(float* __restrict__ out) {
    int b = blockIdx.y;
    int c = blockIdx.x * 128 + threadIdx.x;
    const float* X  = g_x2 + (size_t)b * Ntok * Cdim + c;
    const float* nw = g_nw + b * Ntok;
    const int*   cl = g_cl + b * Ntok;
    float a0 = 0.f, a1 = 0.f;
    for (int n = 0; n < Ntok; n++) {
        float w  = nw[n];
        float xv = X[(size_t)n * Cdim];
        if (cl[n] == 0) a0 = fmaf(xv, w, a0);
        else            a1 = fmaf(xv, w, a1);
    }
    out[((size_t)b * 2 + 0) * Cdim + c] = a0;
    out[((size_t)b * 2 + 1) * Cdim + c] = a1;
}

// ---------------- launch ----------------------------------------------------
extern "C" void kernel_launch(void* const* d_in, const int* in_sizes, int n_in,
                              void* d_out, int out_size) {
    const float* x     = (const float*)d_in[0];
    const float* cw    = (const float*)d_in[1];
    const float* gma   = (const float*)d_in[2];
    const float* bta   = (const float*)d_in[3];
    const float* sw    = (const float*)d_in[4];
    const float* sb    = (const float*)d_in[5];
    const float* noise = (const float*)d_in[6];
    float* out = (float*)d_out;

    cudaFuncSetAttribute(k_conv_mma, cudaFuncAttributeMaxDynamicSharedMemorySize, SMEM_DYN);
    cudaFuncSetAttribute(k_gram_mma, cudaFuncAttributeMaxDynamicSharedMemorySize, SMEM_DYN);

    k_init<<<1, 32>>>();
    k_splitw<<<(3 * Cdim * Cdim + 255) / 256, 256>>>(cw);
    k_split_in<<<(BN * Cdim / 4) / 256, 256>>>(x);

    dim3 gc(Cdim / 128, BN / 128);      // (6, 256)
    k_conv_mma<<<gc, 256, SMEM_DYN>>>(x);

    k_ln<<<BN, 256>>>(gma, bta, sw, sb);
    k_split_x2<<<(BN * Cdim / 4) / 256, 256>>>();

    dim3 gg(136, 1, Bsz);               // upper-triangle tiles x batches
    k_gram_mma<<<gg, 256, SMEM_DYN>>>();

    dim3 gr(Ntok, Bsz);
    k_top3<<<gr, 256>>>(noise);
    k_dmin<<<gr, 256>>>();
    k_top2<<<Bsz, 256>>>();
    k_assign<<<BN / 256, 256>>>();
    k_norm<<<BN / 256, 256>>>(out, out_size);
    dim3 gm(Cdim / 128, Bsz);
    k_merge<<<gm, 128>>>(out);
}

// round 13
// speedup vs baseline: 2.9904x; 1.1824x over previous
#include <cuda_runtime.h>
#include <cuda_bf16.h>
#include <math.h>
#include <stdint.h>

#define Bsz  16
#define Ntok 2048
#define Cdim 768
#define BN   (Bsz*Ntok)

// ---------------- scratch (static device globals; no allocation) ------------
__device__ float g_y [(size_t)BN*Cdim];                 // conv+residual output
__device__ float g_x2[(size_t)BN*Cdim];                 // layernormed x
__device__ __align__(16) __nv_bfloat16 g_xh[(size_t)BN*Cdim];   // hi split
__device__ __align__(16) __nv_bfloat16 g_xl[(size_t)BN*Cdim];   // lo split
__device__ __align__(16) __nv_bfloat16 g_wh[3*Cdim*Cdim];       // W hi [tap][co][ci]
__device__ __align__(16) __nv_bfloat16 g_wl[3*Cdim*Cdim];       // W lo
__device__ float g_dist[(size_t)Bsz*Ntok*Ntok];         // 268 MB distance matrix
__device__ float g_tw [BN];
__device__ float g_sq [BN];
__device__ float g_den[BN];
__device__ float g_sc [BN];
__device__ float g_dmax[Bsz];
__device__ int   g_idn[Bsz*2];
__device__ float g_aw [Bsz*2];
__device__ int   g_cl [BN];
__device__ float g_nw [BN];

// ---------------- mma/ldmatrix/cp.async helpers ------------------------------
__device__ __forceinline__ uint32_t smem_u32(const void* p) {
    uint32_t a;
    asm("{ .reg .u64 t; cvta.to.shared.u64 t, %1; cvt.u32.u64 %0, t; }"
        : "=r"(a) : "l"(p));
    return a;
}

__device__ __forceinline__ void cpa16(uint32_t d, const void* s, int sz) {
    asm volatile("cp.async.cg.shared.global [%0], [%1], 16, %2;"
                 :: "r"(d), "l"(s), "r"(sz));
}

__device__ __forceinline__ void ldm4(uint32_t* r, uint32_t a) {
    asm volatile("ldmatrix.sync.aligned.m8n8.x4.shared.b16 {%0,%1,%2,%3}, [%4];"
                 : "=r"(r[0]), "=r"(r[1]), "=r"(r[2]), "=r"(r[3]) : "r"(a));
}

__device__ __forceinline__ void mma16816(float* c, const uint32_t* a, const uint32_t* b) {
    asm volatile(
        "mma.sync.aligned.m16n8k16.row.col.f32.bf16.bf16.f32 "
        "{%0,%1,%2,%3}, {%4,%5,%6,%7}, {%8,%9}, {%0,%1,%2,%3};"
        : "+f"(c[0]), "+f"(c[1]), "+f"(c[2]), "+f"(c[3])
        : "r"(a[0]), "r"(a[1]), "r"(a[2]), "r"(a[3]), "r"(b[0]), "r"(b[1]));
}

// smem geometry: 4 matrices of 128 rows x 32 bf16, row pitch 80B, 2 stages
#define PITCH 80
#define MATB  (128*PITCH)     // 10240
#define A_HI  0
#define A_LO  (1*MATB)
#define B_HI  (2*MATB)
#define B_LO  (3*MATB)
#define STG   (4*MATB)        // 40960
#define SMEM_DYN (2*STG)      // 81920

// ---------------- misc small kernels ----------------------------------------
__global__ void k_init() {
    int t = threadIdx.x;
    if (t < Bsz) g_dmax[t] = 0.0f;
}

__global__ void k_splitw(const float* __restrict__ w) {
    int i = blockIdx.x * 256 + threadIdx.x;
    if (i >= 3 * Cdim * Cdim) return;
    int ci = i % Cdim;
    int co = (i / Cdim) % Cdim;
    int k  = i / (Cdim * Cdim);
    float v = w[((size_t)co * Cdim + ci) * 3 + k];
    __nv_bfloat16 h = __float2bfloat16(v);
    g_wh[i] = h;
    g_wl[i] = __float2bfloat16(v - __bfloat162float(h));
}

__device__ __forceinline__ void split4(const float* src, size_t i) {
    float4 v = *(const float4*)(src + i);
    __nv_bfloat16 h0 = __float2bfloat16(v.x), h1 = __float2bfloat16(v.y);
    __nv_bfloat16 h2 = __float2bfloat16(v.z), h3 = __float2bfloat16(v.w);
    __nv_bfloat162* ph = (__nv_bfloat162*)(g_xh + i);
    __nv_bfloat162* pl = (__nv_bfloat162*)(g_xl + i);
    ph[0] = __nv_bfloat162(h0, h1);
    ph[1] = __nv_bfloat162(h2, h3);
    pl[0] = __nv_bfloat162(__float2bfloat16(v.x - __bfloat162float(h0)),
                           __float2bfloat16(v.y - __bfloat162float(h1)));
    pl[1] = __nv_bfloat162(__float2bfloat16(v.z - __bfloat162float(h2)),
                           __float2bfloat16(v.w - __bfloat162float(h3)));
}

__global__ void __launch_bounds__(256) k_split_in(const float* __restrict__ src) {
    split4(src, ((size_t)blockIdx.x * 256 + threadIdx.x) * 4);
}
__global__ void __launch_bounds__(256) k_split_x2() {
    split4(g_x2, ((size_t)blockIdx.x * 256 + threadIdx.x) * 4);
}

// ---------------- shared GEMM core (per k-chunk compute) ---------------------
__device__ __forceinline__ void gemm_chunk(uint32_t st, int wm, int wn, int l,
                                           float acc[4][4][4]) {
    #pragma unroll
    for (int kh = 0; kh < 2; kh++) {
        uint32_t ah[4][4], al[4][4], bh[4][2], bl[4][2];
        uint32_t aoff = ((l >> 4) * 8 + kh * 16) * 2;
        int arow = wm * 64 + (l & 15);
        #pragma unroll
        for (int mt = 0; mt < 4; mt++) {
            ldm4(ah[mt], st + A_HI + (uint32_t)(arow + mt * 16) * PITCH + aoff);
            ldm4(al[mt], st + A_LO + (uint32_t)(arow + mt * 16) * PITCH + aoff);
        }
        int brow = wn * 32 + (l & 7) + ((l >> 4) & 1) * 8;
        uint32_t boff = (((l >> 3) & 1) * 8 + kh * 16) * 2;
        #pragma unroll
        for (int p = 0; p < 2; p++) {
            uint32_t tmp[4];
            ldm4(tmp, st + B_HI + (uint32_t)(brow + p * 16) * PITCH + boff);
            bh[2 * p][0] = tmp[0]; bh[2 * p][1] = tmp[1];
            bh[2 * p + 1][0] = tmp[2]; bh[2 * p + 1][1] = tmp[3];
            ldm4(tmp, st + B_LO + (uint32_t)(brow + p * 16) * PITCH + boff);
            bl[2 * p][0] = tmp[0]; bl[2 * p][1] = tmp[1];
            bl[2 * p + 1][0] = tmp[2]; bl[2 * p + 1][1] = tmp[3];
        }
        #pragma unroll
        for (int mt = 0; mt < 4; mt++)
            #pragma unroll
            for (int nt = 0; nt < 4; nt++) {
                mma16816(acc[mt][nt], ah[mt], bh[nt]);
                mma16816(acc[mt][nt], ah[mt], bl[nt]);
                mma16816(acc[mt][nt], al[mt], bh[nt]);
            }
    }
}

// ---------------- conv via HMMA: y = x + sum_taps shift(x)*Wk^T --------------
__device__ __forceinline__ void conv_load(uint32_t st, int r, int sg,
                                          int m0, int n0, int c) {
    int tap = c / 24, kc = (c % 24) * 32;
    int m = m0 + r;
    int loc = (m & (Ntok - 1)) + tap - 1;
    bool v = (loc >= 0 && loc < Ntok);
    long long ao = (long long)(m + tap - 1) * Cdim + kc;
    size_t wo = ((size_t)tap * Cdim + n0 + r) * Cdim + kc;
    uint32_t ro = (uint32_t)r * PITCH;
    #pragma unroll
    for (int i = 0; i < 2; i++) {
        int seg = sg + i;
        uint32_t so = ro + seg * 16;
        cpa16(st + A_HI + so, v ? (const void*)(g_xh + ao + seg * 8) : (const void*)g_xh, v ? 16 : 0);
        cpa16(st + A_LO + so, v ? (const void*)(g_xl + ao + seg * 8) : (const void*)g_xl, v ? 16 : 0);
        cpa16(st + B_HI + so, g_wh + wo + seg * 8, 16);
        cpa16(st + B_LO + so, g_wl + wo + seg * 8, 16);
    }
    asm volatile("cp.async.commit_group;");
}

__global__ void __launch_bounds__(256) k_conv_mma(const float* __restrict__ x) {
    extern __shared__ char sm[];
    uint32_t sb = smem_u32(sm);
    int t = threadIdx.x, l = t & 31, w = t >> 5;
    int wm = w & 1, wn = w >> 1;
    int m0 = blockIdx.y * 128, n0 = blockIdx.x * 128;
    int r = t >> 1, sg = (t & 1) * 2;

    float acc[4][4][4];
    #pragma unroll
    for (int i = 0; i < 4; i++)
        #pragma unroll
        for (int j = 0; j < 4; j++)
            #pragma unroll
            for (int q = 0; q < 4; q++) acc[i][j][q] = 0.f;

    const int C = 72;
    conv_load(sb, r, sg, m0, n0, 0);
    for (int c = 0; c < C; c++) {
        asm volatile("cp.async.wait_group 0;");
        __syncthreads();
        if (c + 1 < C)
            conv_load(sb + ((c + 1) & 1) * STG, r, sg, m0, n0, c + 1);
        gemm_chunk(sb + (c & 1) * STG, wm, wn, l, acc);
    }

    #pragma unroll
    for (int mt = 0; mt < 4; mt++)
        #pragma unroll
        for (int nt = 0; nt < 4; nt++) {
            int mm = m0 + wm * 64 + mt * 16 + (l >> 2);
            int nn = n0 + wn * 32 + nt * 8 + (l & 3) * 2;
            size_t o0 = (size_t)mm * Cdim + nn;
            float2 xv = *(const float2*)(x + o0);
            float2 r0 = make_float2(xv.x + acc[mt][nt][0], xv.y + acc[mt][nt][1]);
            *(float2*)(g_y + o0) = r0;
            size_t o1 = o0 + (size_t)8 * Cdim;
            xv = *(const float2*)(x + o1);
            float2 r1 = make_float2(xv.x + acc[mt][nt][2], xv.y + acc[mt][nt][3]);
            *(float2*)(g_y + o1) = r1;
        }
}

// ---------------- LayerNorm + score + sumsq (warp-shuffle reductions) --------
__global__ void __launch_bounds__(256) k_ln(const float* __restrict__ gma,
                                            const float* __restrict__ bta,
                                            const float* __restrict__ sw,
                                            const float* __restrict__ sb) {
    __shared__ float red[16];
    __shared__ float bc[2];
    int row = blockIdx.x;
    const float* x = g_y + (size_t)row * Cdim;
    int t = threadIdx.x, wid = t >> 5, lid = t & 31;
    float v0 = x[t], v1 = x[t + 256], v2 = x[t + 512];
    float s1 = v0 + v1 + v2;
    float s2 = v0 * v0 + v1 * v1 + v2 * v2;
    #pragma unroll
    for (int o = 16; o; o >>= 1) {
        s1 += __shfl_xor_sync(0xffffffffu, s1, o);
        s2 += __shfl_xor_sync(0xffffffffu, s2, o);
    }
    if (lid == 0) { red[wid] = s1; red[8 + wid] = s2; }
    __syncthreads();
    if (wid == 0) {
        float a = (lid < 8) ? red[lid] : 0.f;
        float b = (lid < 8) ? red[8 + lid] : 0.f;
        #pragma unroll
        for (int o = 4; o; o >>= 1) {
            a += __shfl_xor_sync(0xffffffffu, a, o);
            b += __shfl_xor_sync(0xffffffffu, b, o);
        }
        if (lid == 0) {
            float mu = a * (1.f / Cdim);
            float var = b * (1.f / Cdim) - mu * mu;
            bc[0] = mu;
            bc[1] = rsqrtf(var + 1e-5f);
        }
    }
    __syncthreads();
    float mu = bc[0], rstd = bc[1];
    float y0 = (v0 - mu) * rstd * gma[t]       + bta[t];
    float y1 = (v1 - mu) * rstd * gma[t + 256] + bta[t + 256];
    float y2 = (v2 - mu) * rstd * gma[t + 512] + bta[t + 512];
    float* o = g_x2 + (size_t)row * Cdim;
    o[t] = y0; o[t + 256] = y1; o[t + 512] = y2;
    s1 = y0 * sw[t] + y1 * sw[t + 256] + y2 * sw[t + 512];
    s2 = y0 * y0 + y1 * y1 + y2 * y2;
    #pragma unroll
    for (int os = 16; os; os >>= 1) {
        s1 += __shfl_xor_sync(0xffffffffu, s1, os);
        s2 += __shfl_xor_sync(0xffffffffu, s2, os);
    }
    if (lid == 0) { red[wid] = s1; red[8 + wid] = s2; }
    __syncthreads();
    if (t == 0) {
        float a = 0.f, b = 0.f;
        #pragma unroll
        for (int i = 0; i < 8; i++) { a += red[i]; b += red[8 + i]; }
        g_tw[row] = expf(a + sb[0]);
        g_sq[row] = b;
    }
}

// ---------------- gram via HMMA -> distance matrix (triangle+mirror) --------
__device__ __forceinline__ void gram_load(uint32_t st, int r, int sg,
                                          int bz, int m0, int n0, int c) {
    int kc = c * 32;
    size_t ao = ((size_t)(bz * Ntok + m0 + r)) * Cdim + kc;
    size_t bo = ((size_t)(bz * Ntok + n0 + r)) * Cdim + kc;
    uint32_t ro = (uint32_t)r * PITCH;
    #pragma unroll
    for (int i = 0; i < 2; i++) {
        int seg = sg + i;
        uint32_t so = ro + seg * 16;
        cpa16(st + A_HI + so, g_xh + ao + seg * 8, 16);
        cpa16(st + A_LO + so, g_xl + ao + seg * 8, 16);
        cpa16(st + B_HI + so, g_xh + bo + seg * 8, 16);
        cpa16(st + B_LO + so, g_xl + bo + seg * 8, 16);
    }
    asm volatile("cp.async.commit_group;");
}

__global__ void __launch_bounds__(256) k_gram_mma() {
    extern __shared__ char sm[];
    uint32_t sb = smem_u32(sm);
    int t = threadIdx.x, l = t & 31, w = t >> 5;
    int wm = w & 1, wn = w >> 1;

    int rem = blockIdx.x, mi = 0;
    #pragma unroll 1
    while (rem >= 16 - mi) { rem -= 16 - mi; mi++; }
    int ni = mi + rem;
    const int bz = blockIdx.z;
    const int m0 = mi * 128, n0 = ni * 128;
    float* __restrict__ D = g_dist + (size_t)bz * Ntok * Ntok;
    const float* __restrict__ sqb = g_sq + bz * Ntok;
    int r = t >> 1, sg = (t & 1) * 2;

    float acc[4][4][4];
    #pragma unroll
    for (int i = 0; i < 4; i++)
        #pragma unroll
        for (int j = 0; j < 4; j++)
            #pragma unroll
            for (int q = 0; q < 4; q++) acc[i][j][q] = 0.f;

    const int C = 24;
    gram_load(sb, r, sg, bz, m0, n0, 0);
    for (int c = 0; c < C; c++) {
        asm volatile("cp.async.wait_group 0;");
        __syncthreads();
        if (c + 1 < C)
            gram_load(sb + ((c + 1) & 1) * STG, r, sg, bz, m0, n0, c + 1);
        gemm_chunk(sb + (c & 1) * STG, wm, wn, l, acc);
    }

    const float rs = rsqrtf((float)Cdim);
    #pragma unroll
    for (int mt = 0; mt < 4; mt++)
        #pragma unroll
        for (int nt = 0; nt < 4; nt++) {
            int mmb = m0 + wm * 64 + mt * 16 + (l >> 2);
            int nn = n0 + wn * 32 + nt * 8 + (l & 3) * 2;
            float s0 = sqb[nn], s1 = sqb[nn + 1];
            #pragma unroll
            for (int h = 0; h < 2; h++) {
                int M = mmb + h * 8;
                float sn = sqb[M];
                float d0 = sqrtf(fmaxf(sn + s0 - 2.f * acc[mt][nt][2 * h], 0.f)) * rs;
                float d1 = sqrtf(fmaxf(sn + s1 - 2.f * acc[mt][nt][2 * h + 1], 0.f)) * rs;
                *(float2*)(D + (size_t)M * Ntok + nn) = make_float2(d0, d1);
                if (ni > mi) {
                    D[(size_t)nn * Ntok + M]       = d0;
                    D[(size_t)(nn + 1) * Ntok + M] = d1;
                }
            }
        }
}

// ---------------- small helpers for scans -----------------------------------
__device__ __forceinline__ void ins3(float v, float& c0, float& c1, float& c2) {
    if (v < c2) {
        if (v < c1) {
            c2 = c1;
            if (v < c0) { c1 = c0; c0 = v; } else c1 = v;
        } else c2 = v;
    }
}

// ---------------- per-row: top-3 smallest + row max -> density --------------
__global__ void __launch_bounds__(256) k_top3(const float* __restrict__ noise) {
    int n = blockIdx.x, b = blockIdx.y;
    const float* row = g_dist + ((size_t)b * Ntok + n) * Ntok;
    int t = threadIdx.x;
    float c0 = 3e38f, c1 = 3e38f, c2 = 3e38f, mx = 0.f;
    for (int m = t; m < Ntok; m += 256) {
        float v = row[m];
        mx = fmaxf(mx, v);
        ins3(v, c0, c1, c2);
    }
    __shared__ float s0[256], s1[256], s2[256], smx[256];
    s0[t] = c0; s1[t] = c1; s2[t] = c2; smx[t] = mx;
    __syncthreads();
    for (int h = 128; h; h >>= 1) {
        if (t < h) {
            float b0 = s0[t + h], b1 = s1[t + h], b2 = s2[t + h];
            c0 = s0[t]; c1 = s1[t]; c2 = s2[t];
            ins3(b0, c0, c1, c2); ins3(b1, c0, c1, c2); ins3(b2, c0, c1, c2);
            s0[t] = c0; s1[t] = c1; s2[t] = c2;
            smx[t] = fmaxf(smx[t], smx[t + h]);
        }
        __syncthreads();
    }
    if (t == 0) {
        float m3 = (s0[0] * s0[0] + s1[0] * s1[0] + s2[0] * s2[0]) * (1.f / 3.f);
        g_den[b * Ntok + n] = expf(-m3) + noise[b * Ntok + n] * 1e-6f;
        atomicMax((int*)&g_dmax[b], __float_as_int(smx[0]));
    }
}

// ---------------- per-row: dist to nearest higher-density -> score ----------
__global__ void __launch_bounds__(256) k_dmin() {
    int n = blockIdx.x, b = blockIdx.y;
    const float* row = g_dist + ((size_t)b * Ntok + n) * Ntok;
    const float* den = g_den + b * Ntok;
    float dn = den[n];
    float dmax = g_dmax[b];
    int t = threadIdx.x;
    float mn = 3e38f;
    for (int m = t; m < Ntok; m += 256) {
        float v = (den[m] > dn) ? row[m] : dmax;
        mn = fminf(mn, v);
    }
    __shared__ float s[256];
    s[t] = mn; __syncthreads();
    for (int h = 128; h; h >>= 1) {
        if (t < h) s[t] = fminf(s[t], s[t + h]);
        __syncthreads();
    }
    if (t == 0) g_sc[b * Ntok + n] = s[0] * dn;
}

// ---------------- per-batch: top-2 score indices ----------------------------
__global__ void __launch_bounds__(256) k_top2() {
    int b = blockIdx.x, t = threadIdx.x;
    const float* sc = g_sc + b * Ntok;
    __shared__ float bv[256];
    __shared__ int   bi[256];
    float v = -3e38f; int ii = 0x7fffffff;
    for (int m = t; m < Ntok; m += 256) {
        float x = sc[m];
        if (x > v) { v = x; ii = m; }
    }
    bv[t] = v; bi[t] = ii; __syncthreads();
    for (int h = 128; h; h >>= 1) {
        if (t < h) {
            if (bv[t + h] > bv[t] || (bv[t + h] == bv[t] && bi[t + h] < bi[t])) {
                bv[t] = bv[t + h]; bi[t] = bi[t + h];
            }
        }
        __syncthreads();
    }
    int i0 = bi[0];
    __syncthreads();
    v = -3e38f; ii = 0x7fffffff;
    for (int m = t; m < Ntok; m += 256) {
        if (m == i0) continue;
        float x = sc[m];
        if (x > v) { v = x; ii = m; }
    }
    bv[t] = v; bi[t] = ii; __syncthreads();
    for (int h = 128; h; h >>= 1) {
        if (t < h) {
            if (bv[t + h] > bv[t] || (bv[t + h] == bv[t] && bi[t + h] < bi[t])) {
                bv[t] = bv[t + h]; bi[t] = bi[t + h];
            }
        }
        __syncthreads();
    }
    if (t == 0) {
        g_idn[2 * b]     = i0;
        g_idn[2 * b + 1] = bi[0];
        g_aw[2 * b]      = 1e-6f;
        g_aw[2 * b + 1]  = 1e-6f;
    }
}

// ---------------- assign clusters + accumulate cluster weights --------------
__global__ void __launch_bounds__(256) k_assign() {
    int tk = blockIdx.x * 256 + threadIdx.x;
    int b = tk >> 11, n = tk & (Ntok - 1);
    int i0 = g_idn[2 * b], i1 = g_idn[2 * b + 1];
    float d0 = g_dist[((size_t)b * Ntok + i0) * Ntok + n];
    float d1 = g_dist[((size_t)b * Ntok + i1) * Ntok + n];
    int cl = (d1 < d0) ? 1 : 0;
    if (n == i0) cl = 0;
    if (n == i1) cl = 1;
    g_cl[tk] = cl;
    float w = g_tw[tk];
    float w0 = cl ? 0.f : w;
    float w1 = cl ? w : 0.f;
    #pragma unroll
    for (int o = 16; o; o >>= 1) {
        w0 += __shfl_down_sync(0xffffffffu, w0, o);
        w1 += __shfl_down_sync(0xffffffffu, w1, o);
    }
    if ((threadIdx.x & 31) == 0) {
        atomicAdd(&g_aw[2 * b],     w0);
        atomicAdd(&g_aw[2 * b + 1], w1);
    }
}

// ---------------- normalized weights + aux outputs --------------------------
__global__ void __launch_bounds__(256) k_norm(float* __restrict__ out, int out_size) {
    int tk = blockIdx.x * 256 + threadIdx.x;
    int b = tk >> 11;
    int cl = g_cl[tk];
    float nw = g_tw[tk] / g_aw[2 * b + cl];
    g_nw[tk] = nw;
    const int XM = Bsz * 2 * Cdim;       // 24576
    if (out_size >= XM + BN)       out[XM + tk]      = nw;
    if (out_size >= XM + 2 * BN)   out[XM + BN + tk] = (float)cl;
}

// ---------------- zero merged-x slab, then parallel weighted merge ----------
__global__ void __launch_bounds__(128) k_zero(float* __restrict__ out) {
    int i = blockIdx.x * 128 + threadIdx.x;
    if (i < Bsz * 2 * Cdim) out[i] = 0.f;
}

__global__ void __launch_bounds__(128) k_merge(float* __restrict__ out) {
    int b = blockIdx.y;
    int c = blockIdx.x * 128 + threadIdx.x;
    int n0 = blockIdx.z * 256;
    const float* X  = g_x2 + ((size_t)b * Ntok + n0) * Cdim + c;
    const float* nw = g_nw + b * Ntok + n0;
    const int*   cl = g_cl + b * Ntok + n0;
    float a0 = 0.f, a1 = 0.f;
    for (int n = 0; n < 256; n++) {
        float w  = nw[n];
        float xv = X[(size_t)n * Cdim];
        if (cl[n] == 0) a0 = fmaf(xv, w, a0);
        else            a1 = fmaf(xv, w, a1);
    }
    atomicAdd(&out[((size_t)b * 2 + 0) * Cdim + c], a0);
    atomicAdd(&out[((size_t)b * 2 + 1) * Cdim + c], a1);
}

// ---------------- launch ----------------------------------------------------
extern "C" void kernel_launch(void* const* d_in, const int* in_sizes, int n_in,
                              void* d_out, int out_size) {
    const float* x     = (const float*)d_in[0];
    const float* cw    = (const float*)d_in[1];
    const float* gma   = (const float*)d_in[2];
    const float* bta   = (const float*)d_in[3];
    const float* sw    = (const float*)d_in[4];
    const float* sb    = (const float*)d_in[5];
    const float* noise = (const float*)d_in[6];
    float* out = (float*)d_out;

    cudaFuncSetAttribute(k_conv_mma, cudaFuncAttributeMaxDynamicSharedMemorySize, SMEM_DYN);
    cudaFuncSetAttribute(k_gram_mma, cudaFuncAttributeMaxDynamicSharedMemorySize, SMEM_DYN);

    k_init<<<1, 32>>>();
    k_splitw<<<(3 * Cdim * Cdim + 255) / 256, 256>>>(cw);
    k_split_in<<<(BN * Cdim / 4) / 256, 256>>>(x);

    dim3 gc(Cdim / 128, BN / 128);      // (6, 256)
    k_conv_mma<<<gc, 256, SMEM_DYN>>>(x);

    k_ln<<<BN, 256>>>(gma, bta, sw, sb);
    k_split_x2<<<(BN * Cdim / 4) / 256, 256>>>();

    dim3 gg(136, 1, Bsz);               // upper-triangle tiles x batches
    k_gram_mma<<<gg, 256, SMEM_DYN>>>();

    dim3 gr(Ntok, Bsz);
    k_top3<<<gr, 256>>>(noise);
    k_dmin<<<gr, 256>>>();
    k_top2<<<Bsz, 256>>>();
    k_assign<<<BN / 256, 256>>>();
    k_norm<<<BN / 256, 256>>>(out, out_size);
    k_zero<<<(Bsz * 2 * Cdim + 127) / 128, 128>>>(out);
    dim3 gm(Cdim / 128, Bsz, Ntok / 256);   // (6, 16, 8)
    k_merge<<<gm, 128>>>(out);
}